// round 14
// baseline (speedup 1.0000x reference)
#include <cuda_runtime.h>
#include <cuda_fp16.h>

// Problem constants (BOWRegressionMulti: T=200, B=1024, V=50000, L=512, PAD=1)
#define T_TOK 200
#define B_SZ  1024
#define V_SZ  50000
#define L_SZ  512
#define PAD_TOK 1
#define V_WORDS 1563                       // ceil(V/32)

#define VTILES2 391                        // ceil(V/128)
#define LTILES  (L_SZ / 64)                // 8
#define TR_BLOCKS (VTILES2 * LTILES)       // 3128 transpose blocks
#define S_STRIDE 129                       // smem row stride (words): conflict-free

// Scratch (static device globals — no allocs):
__device__ __half   g_Wt_h[(size_t)V_SZ * L_SZ];   // 51.2 MB transposed fp16 weights
__device__ unsigned g_toks[B_SZ][T_TOK];           // deduped uint2-offsets (v*128)
__device__ int      g_cnt[B_SZ];

// ---------------------------------------------------------------------------
// K1 (fused prep): blocks [0, TR_BLOCKS) transpose a 64(label) x 128(vocab)
// tile of W[L,V] f32 into Wt[V,L] f16. All 8 LDG.128 hoisted into registers
// (128B MLP/thread), convert-on-read into a half2 [lp][v] smem tile with
// stride-129 (conflict-free write-phase LDS). Blocks [TR_BLOCKS, +B_SZ) do
// per-row token dedupe in the same smem union.
// ---------------------------------------------------------------------------
__global__ __launch_bounds__(256) void bow_prep_kernel(
    const float* __restrict__ W,           // [L, V] f32
    const int*   __restrict__ text)        // [T, B] int32
{
    __shared__ unsigned s_buf[32 * S_STRIDE];   // 16.5 KB half2 tile / bitmap
    const int bid = blockIdx.x;
    const int tid = threadIdx.x;

    if (bid < TR_BLOCKS) {
        // ---------------- transpose role ----------------
        const int v0 = (bid % VTILES2) * 128;
        const int l0 = (bid / VTILES2) * 64;
        const int tx = tid & 31;           // float4 slot: v = v0 + tx*4
        const int ty = tid >> 5;           // base label-pair (0..7)
        const int v  = v0 + tx * 4;        // V%4==0 -> all-or-none per float4
        const bool vok = (v < V_SZ);

        // Batch-load all 8 float4 (4 label-pairs x 2 rows) into registers.
        float4 ra[4], rb[4];
        #pragma unroll
        for (int p = 0; p < 4; p++) {
            const int l = l0 + 2 * (ty + p * 8);
            ra[p] = make_float4(0.f, 0.f, 0.f, 0.f);
            rb[p] = make_float4(0.f, 0.f, 0.f, 0.f);
            if (vok) {
                ra[p] = __ldcs((const float4*)(W + (size_t)l       * V_SZ + v));
                rb[p] = __ldcs((const float4*)(W + (size_t)(l + 1) * V_SZ + v));
            }
        }

        // Convert + stage: s_buf[lp*S_STRIDE + vi] = half2(W[l][v], W[l+1][v])
        #pragma unroll
        for (int p = 0; p < 4; p++) {
            const int lp = ty + p * 8;
            __half2 h0 = __floats2half2_rn(ra[p].x, rb[p].x);
            __half2 h1 = __floats2half2_rn(ra[p].y, rb[p].y);
            __half2 h2 = __floats2half2_rn(ra[p].z, rb[p].z);
            __half2 h3 = __floats2half2_rn(ra[p].w, rb[p].w);
            s_buf[lp * S_STRIDE + tx * 4 + 0] = *(unsigned*)&h0;
            s_buf[lp * S_STRIDE + tx * 4 + 1] = *(unsigned*)&h1;
            s_buf[lp * S_STRIDE + tx * 4 + 2] = *(unsigned*)&h2;
            s_buf[lp * S_STRIDE + tx * 4 + 3] = *(unsigned*)&h3;
        }
        __syncthreads();

        // Write: item k -> (vr = k>>3, w = k&7): uint4 = 4 half2 = labels
        // l0+8w .. l0+8w+7 of Wt row v0+vr. Banks (4w+c+vr)%32: conflict-free.
        #pragma unroll
        for (int k = tid; k < 1024; k += 256) {
            const int vr = k >> 3;
            const int w  = k & 7;
            if (v0 + vr < V_SZ) {
                uint4 pkt;
                pkt.x = s_buf[(4 * w + 0) * S_STRIDE + vr];
                pkt.y = s_buf[(4 * w + 1) * S_STRIDE + vr];
                pkt.z = s_buf[(4 * w + 2) * S_STRIDE + vr];
                pkt.w = s_buf[(4 * w + 3) * S_STRIDE + vr];
                *(uint4*)(g_Wt_h + (size_t)(v0 + vr) * L_SZ + l0 + 8 * w) = pkt;
            }
        }
    } else {
        // ---------------- dedupe role ----------------
        const int b = bid - TR_BLOCKS;
        unsigned int* bitmap = s_buf;      // 1563 words fit in 4128-word buffer
        __shared__ int cnt;

        for (int i = tid; i < V_WORDS; i += 256) bitmap[i] = 0u;
        if (tid == 0) cnt = 0;
        __syncthreads();

        if (tid < T_TOK) {
            int v = text[(size_t)tid * B_SZ + b];
            if (v != PAD_TOK && (unsigned)v < (unsigned)V_SZ) {
                unsigned int bit = 1u << (v & 31);
                unsigned int old = atomicOr(&bitmap[v >> 5], bit);
                if (!(old & bit)) {
                    int idx = atomicAdd(&cnt, 1);
                    g_toks[b][idx] = (unsigned)v * (L_SZ / 4);  // uint2-offset units
                }
            }
        }
        __syncthreads();
        if (tid == 0) g_cnt[b] = cnt;
    }
}

// ---------------------------------------------------------------------------
// K2: gather (R10/R13, proven ~19.7us @ ~91% LTS ceiling). One block = one
// row. 256 threads: g = tid>>7 = token parity, t = tid&127 owns labels
// [4t, 4t+4) via one uint2 (8B) load per token. Depth-2 fp16 pre-add tree,
// fp32 accumulation; parity-1 partials staged in smem, combined with bias.
// __launch_bounds__(256, 8) pins regs <= 32.
// ---------------------------------------------------------------------------
__global__ __launch_bounds__(256, 8) void bow_gather_kernel(
    const float* __restrict__ bias,        // [L]
    float* __restrict__ out)               // [B, L]
{
    __shared__ unsigned offs[T_TOK];
    __shared__ float4 part[128];           // parity-1 partials (2 KB)

    const int b   = blockIdx.x;
    const int tid = threadIdx.x;
    const int g   = tid >> 7;              // token parity
    const int t   = tid & 127;             // label group: labels [4t, 4t+4)

    const int n = g_cnt[b];
    if (tid < T_TOK) offs[tid] = g_toks[b][tid];
    __syncthreads();

    // Per-thread base: address = base + off*8 -> single IMAD.WIDE per load.
    const uint2* Wt_t = (const uint2*)g_Wt_h + t;

    const int m = (n - g + 1) >> 1;        // count of own-parity tokens

    float2 a0 = make_float2(0.f, 0.f);
    float2 a1 = make_float2(0.f, 0.f);
    float2 a2 = make_float2(0.f, 0.f);
    float2 a3 = make_float2(0.f, 0.f);

    int i = 0;
    for (; i + 8 <= m; i += 8) {
        uint2 u0 = Wt_t[offs[2 * (i + 0) + g]];
        uint2 u1 = Wt_t[offs[2 * (i + 1) + g]];
        uint2 u2 = Wt_t[offs[2 * (i + 2) + g]];
        uint2 u3 = Wt_t[offs[2 * (i + 3) + g]];
        uint2 u4 = Wt_t[offs[2 * (i + 4) + g]];
        uint2 u5 = Wt_t[offs[2 * (i + 5) + g]];
        uint2 u6 = Wt_t[offs[2 * (i + 6) + g]];
        uint2 u7 = Wt_t[offs[2 * (i + 7) + g]];
        __half2 p0x = __hadd2(*(__half2*)&u0.x, *(__half2*)&u1.x);
        __half2 p0y = __hadd2(*(__half2*)&u0.y, *(__half2*)&u1.y);
        __half2 p1x = __hadd2(*(__half2*)&u2.x, *(__half2*)&u3.x);
        __half2 p1y = __hadd2(*(__half2*)&u2.y, *(__half2*)&u3.y);
        __half2 p2x = __hadd2(*(__half2*)&u4.x, *(__half2*)&u5.x);
        __half2 p2y = __hadd2(*(__half2*)&u4.y, *(__half2*)&u5.y);
        __half2 p3x = __hadd2(*(__half2*)&u6.x, *(__half2*)&u7.x);
        __half2 p3y = __hadd2(*(__half2*)&u6.y, *(__half2*)&u7.y);
        __half2 q0x = __hadd2(p0x, p1x);
        __half2 q0y = __hadd2(p0y, p1y);
        __half2 q1x = __hadd2(p2x, p3x);
        __half2 q1y = __hadd2(p2y, p3y);
        float2 f;
        f = __half22float2(q0x); a0.x += f.x; a0.y += f.y;
        f = __half22float2(q0y); a1.x += f.x; a1.y += f.y;
        f = __half22float2(q1x); a2.x += f.x; a2.y += f.y;
        f = __half22float2(q1y); a3.x += f.x; a3.y += f.y;
    }
    for (; i + 2 <= m; i += 2) {
        uint2 u0 = Wt_t[offs[2 * (i + 0) + g]];
        uint2 u1 = Wt_t[offs[2 * (i + 1) + g]];
        __half2 px = __hadd2(*(__half2*)&u0.x, *(__half2*)&u1.x);
        __half2 py = __hadd2(*(__half2*)&u0.y, *(__half2*)&u1.y);
        float2 f;
        f = __half22float2(px); a0.x += f.x; a0.y += f.y;
        f = __half22float2(py); a1.x += f.x; a1.y += f.y;
    }
    if (i < m) {
        uint2 u = Wt_t[offs[2 * i + g]];
        float2 f;
        f = __half22float2(*(__half2*)&u.x); a2.x += f.x; a2.y += f.y;
        f = __half22float2(*(__half2*)&u.y); a3.x += f.x; a3.y += f.y;
    }

    float4 s;
    s.x = a0.x + a2.x;
    s.y = a0.y + a2.y;
    s.z = a1.x + a3.x;
    s.w = a1.y + a3.y;

    if (g == 1) part[t] = s;
    __syncthreads();

    if (g == 0) {
        const float4 bs = ((const float4*)bias)[t];
        const float4 p  = part[t];
        float4 r;
        r.x = bs.x + s.x + p.x;
        r.y = bs.y + s.y + p.y;
        r.z = bs.z + s.z + p.z;
        r.w = bs.w + s.w + p.w;
        ((float4*)out)[(size_t)b * (L_SZ / 4) + t] = r;
    }
}

// ---------------------------------------------------------------------------
// Launch: fused prep (transpose + dedupe) then gather. Graph-capturable.
// Inputs: [0] text int32 [T,B], [1] W f32 [L,V], [2] b f32 [L].
// ---------------------------------------------------------------------------
extern "C" void kernel_launch(void* const* d_in, const int* in_sizes, int n_in,
                              void* d_out, int out_size) {
    const int*   text = (const int*)d_in[0];
    const float* W    = (const float*)d_in[1];
    const float* bias = (const float*)d_in[2];
    float*       out  = (float*)d_out;

    bow_prep_kernel<<<TR_BLOCKS + B_SZ, 256>>>(W, text);
    bow_gather_kernel<<<B_SZ, 256>>>(bias, out);
}

// round 15
// speedup vs baseline: 1.0562x; 1.0562x over previous
#include <cuda_runtime.h>
#include <cuda_fp16.h>

// Problem constants (BOWRegressionMulti: T=200, B=1024, V=50000, L=512, PAD=1)
#define T_TOK 200
#define B_SZ  1024
#define V_SZ  50000
#define L_SZ  512
#define PAD_TOK 1
#define V_WORDS 1563                       // ceil(V/32)

#define VTILES 782                         // ceil(V/64)
#define LTILES (L_SZ / 64)                 // 8
#define TR_BLOCKS (VTILES * LTILES)        // 6256 transpose blocks

// Scratch (static device globals — no allocs):
__device__ __half   g_Wt_h[(size_t)V_SZ * L_SZ];   // 51.2 MB transposed fp16 weights
__device__ unsigned g_toks[B_SZ][T_TOK];           // deduped uint2-offsets (v*128)
__device__ int      g_cnt[B_SZ];

// ---------------------------------------------------------------------------
// K1 (fused prep): blocks [0, TR_BLOCKS) transpose a 64(label) x 64(vocab)
// tile of W[L,V] f32 into Wt[V,L] f16 with half-precision smem staging
// (8.83 KB -> 8 blocks/SM). All 4 LDG.128 hoisted back-to-back (64B MLP per
// thread, only 16 live regs) before conversion. Stride-69 staging makes the
// write-phase scalar LDS conflict-free. Blocks [TR_BLOCKS, +B_SZ) do per-row
// token dedupe in the same smem union.
// ---------------------------------------------------------------------------
__global__ __launch_bounds__(256) void bow_prep_kernel(
    const float* __restrict__ W,           // [L, V] f32
    const int*   __restrict__ text)        // [T, B] int32
{
    __shared__ unsigned s_buf[32 * 69];    // 8.83 KB: [lp][v] half2 tile / bitmap
    const int bid = blockIdx.x;
    const int tid = threadIdx.x;

    if (bid < TR_BLOCKS) {
        // ---------------- transpose role ----------------
        const int v0 = (bid % VTILES) * 64;
        const int l0 = (bid / VTILES) * 64;
        const int tx = tid & 15;           // float4 slot: v = v0 + tx*4
        const int ty = tid >> 4;           // base label-pair (0..15)
        const int v  = v0 + tx * 4;        // V%4==0 -> all-or-none per float4
        const bool vok = (v < V_SZ);

        // Hoist all 4 LDG.128 (2 label-pairs x 2 adjacent rows) back-to-back.
        float4 ra0 = make_float4(0.f, 0.f, 0.f, 0.f);
        float4 rb0 = ra0, ra1 = ra0, rb1 = ra0;
        const int la = l0 + 2 * ty;            // pair 0: rows la, la+1
        const int lb = l0 + 2 * (ty + 16);     // pair 1: rows lb, lb+1
        if (vok) {
            ra0 = __ldcs((const float4*)(W + (size_t)la       * V_SZ + v));
            rb0 = __ldcs((const float4*)(W + (size_t)(la + 1) * V_SZ + v));
            ra1 = __ldcs((const float4*)(W + (size_t)lb       * V_SZ + v));
            rb1 = __ldcs((const float4*)(W + (size_t)(lb + 1) * V_SZ + v));
        }

        // Convert + stage: s_buf[lp*69 + vi] = half2(W[2lp][v], W[2lp+1][v])
        {
            const int lp = ty;
            __half2 h0 = __floats2half2_rn(ra0.x, rb0.x);
            __half2 h1 = __floats2half2_rn(ra0.y, rb0.y);
            __half2 h2 = __floats2half2_rn(ra0.z, rb0.z);
            __half2 h3 = __floats2half2_rn(ra0.w, rb0.w);
            s_buf[lp * 69 + tx * 4 + 0] = *(unsigned*)&h0;
            s_buf[lp * 69 + tx * 4 + 1] = *(unsigned*)&h1;
            s_buf[lp * 69 + tx * 4 + 2] = *(unsigned*)&h2;
            s_buf[lp * 69 + tx * 4 + 3] = *(unsigned*)&h3;
        }
        {
            const int lp = ty + 16;
            __half2 h0 = __floats2half2_rn(ra1.x, rb1.x);
            __half2 h1 = __floats2half2_rn(ra1.y, rb1.y);
            __half2 h2 = __floats2half2_rn(ra1.z, rb1.z);
            __half2 h3 = __floats2half2_rn(ra1.w, rb1.w);
            s_buf[lp * 69 + tx * 4 + 0] = *(unsigned*)&h0;
            s_buf[lp * 69 + tx * 4 + 1] = *(unsigned*)&h1;
            s_buf[lp * 69 + tx * 4 + 2] = *(unsigned*)&h2;
            s_buf[lp * 69 + tx * 4 + 3] = *(unsigned*)&h3;
        }
        __syncthreads();

        // Write: item k -> (vr = k>>3, w = k&7): uint4 = 4 half2 = labels
        // l0+8w .. l0+8w+7 of Wt row v0+vr. Stride-69 LDS is conflict-free.
        #pragma unroll
        for (int k = tid; k < 512; k += 256) {
            const int vr = k >> 3;
            const int w  = k & 7;
            if (v0 + vr < V_SZ) {
                uint4 pkt;
                pkt.x = s_buf[(4 * w + 0) * 69 + vr];
                pkt.y = s_buf[(4 * w + 1) * 69 + vr];
                pkt.z = s_buf[(4 * w + 2) * 69 + vr];
                pkt.w = s_buf[(4 * w + 3) * 69 + vr];
                *(uint4*)(g_Wt_h + (size_t)(v0 + vr) * L_SZ + l0 + 8 * w) = pkt;
            }
        }
    } else {
        // ---------------- dedupe role ----------------
        const int b = bid - TR_BLOCKS;
        unsigned int* bitmap = s_buf;      // 1563 words fit in 2208-word buffer
        __shared__ int cnt;

        for (int i = tid; i < V_WORDS; i += 256) bitmap[i] = 0u;
        if (tid == 0) cnt = 0;
        __syncthreads();

        if (tid < T_TOK) {
            int v = text[(size_t)tid * B_SZ + b];
            if (v != PAD_TOK && (unsigned)v < (unsigned)V_SZ) {
                unsigned int bit = 1u << (v & 31);
                unsigned int old = atomicOr(&bitmap[v >> 5], bit);
                if (!(old & bit)) {
                    int idx = atomicAdd(&cnt, 1);
                    g_toks[b][idx] = (unsigned)v * (L_SZ / 4);  // uint2-offset units
                }
            }
        }
        __syncthreads();
        if (tid == 0) g_cnt[b] = cnt;
    }
}

// ---------------------------------------------------------------------------
// K2: gather (proven ~19.7us @ ~91% LTS ceiling). One block = one row.
// 256 threads: g = tid>>7 = token parity, t = tid&127 owns labels [4t, 4t+4)
// via one uint2 (8B) load per token. Depth-2 fp16 pre-add tree, fp32
// accumulation; parity-1 partials staged in smem, combined with bias.
// __launch_bounds__(256, 8) pins regs <= 32.
// ---------------------------------------------------------------------------
__global__ __launch_bounds__(256, 8) void bow_gather_kernel(
    const float* __restrict__ bias,        // [L]
    float* __restrict__ out)               // [B, L]
{
    __shared__ unsigned offs[T_TOK];
    __shared__ float4 part[128];           // parity-1 partials (2 KB)

    const int b   = blockIdx.x;
    const int tid = threadIdx.x;
    const int g   = tid >> 7;              // token parity
    const int t   = tid & 127;             // label group: labels [4t, 4t+4)

    const int n = g_cnt[b];
    if (tid < T_TOK) offs[tid] = g_toks[b][tid];
    __syncthreads();

    // Per-thread base: address = base + off*8 -> single IMAD.WIDE per load.
    const uint2* Wt_t = (const uint2*)g_Wt_h + t;

    const int m = (n - g + 1) >> 1;        // count of own-parity tokens

    float2 a0 = make_float2(0.f, 0.f);
    float2 a1 = make_float2(0.f, 0.f);
    float2 a2 = make_float2(0.f, 0.f);
    float2 a3 = make_float2(0.f, 0.f);

    int i = 0;
    for (; i + 8 <= m; i += 8) {
        uint2 u0 = Wt_t[offs[2 * (i + 0) + g]];
        uint2 u1 = Wt_t[offs[2 * (i + 1) + g]];
        uint2 u2 = Wt_t[offs[2 * (i + 2) + g]];
        uint2 u3 = Wt_t[offs[2 * (i + 3) + g]];
        uint2 u4 = Wt_t[offs[2 * (i + 4) + g]];
        uint2 u5 = Wt_t[offs[2 * (i + 5) + g]];
        uint2 u6 = Wt_t[offs[2 * (i + 6) + g]];
        uint2 u7 = Wt_t[offs[2 * (i + 7) + g]];
        __half2 p0x = __hadd2(*(__half2*)&u0.x, *(__half2*)&u1.x);
        __half2 p0y = __hadd2(*(__half2*)&u0.y, *(__half2*)&u1.y);
        __half2 p1x = __hadd2(*(__half2*)&u2.x, *(__half2*)&u3.x);
        __half2 p1y = __hadd2(*(__half2*)&u2.y, *(__half2*)&u3.y);
        __half2 p2x = __hadd2(*(__half2*)&u4.x, *(__half2*)&u5.x);
        __half2 p2y = __hadd2(*(__half2*)&u4.y, *(__half2*)&u5.y);
        __half2 p3x = __hadd2(*(__half2*)&u6.x, *(__half2*)&u7.x);
        __half2 p3y = __hadd2(*(__half2*)&u6.y, *(__half2*)&u7.y);
        __half2 q0x = __hadd2(p0x, p1x);
        __half2 q0y = __hadd2(p0y, p1y);
        __half2 q1x = __hadd2(p2x, p3x);
        __half2 q1y = __hadd2(p2y, p3y);
        float2 f;
        f = __half22float2(q0x); a0.x += f.x; a0.y += f.y;
        f = __half22float2(q0y); a1.x += f.x; a1.y += f.y;
        f = __half22float2(q1x); a2.x += f.x; a2.y += f.y;
        f = __half22float2(q1y); a3.x += f.x; a3.y += f.y;
    }
    for (; i + 2 <= m; i += 2) {
        uint2 u0 = Wt_t[offs[2 * (i + 0) + g]];
        uint2 u1 = Wt_t[offs[2 * (i + 1) + g]];
        __half2 px = __hadd2(*(__half2*)&u0.x, *(__half2*)&u1.x);
        __half2 py = __hadd2(*(__half2*)&u0.y, *(__half2*)&u1.y);
        float2 f;
        f = __half22float2(px); a0.x += f.x; a0.y += f.y;
        f = __half22float2(py); a1.x += f.x; a1.y += f.y;
    }
    if (i < m) {
        uint2 u = Wt_t[offs[2 * i + g]];
        float2 f;
        f = __half22float2(*(__half2*)&u.x); a2.x += f.x; a2.y += f.y;
        f = __half22float2(*(__half2*)&u.y); a3.x += f.x; a3.y += f.y;
    }

    float4 s;
    s.x = a0.x + a2.x;
    s.y = a0.y + a2.y;
    s.z = a1.x + a3.x;
    s.w = a1.y + a3.y;

    if (g == 1) part[t] = s;
    __syncthreads();

    if (g == 0) {
        const float4 bs = ((const float4*)bias)[t];
        const float4 p  = part[t];
        float4 r;
        r.x = bs.x + s.x + p.x;
        r.y = bs.y + s.y + p.y;
        r.z = bs.z + s.z + p.z;
        r.w = bs.w + s.w + p.w;
        ((float4*)out)[(size_t)b * (L_SZ / 4) + t] = r;
    }
}

// ---------------------------------------------------------------------------
// Launch: fused prep (transpose + dedupe) then gather. Graph-capturable.
// Inputs: [0] text int32 [T,B], [1] W f32 [L,V], [2] b f32 [L].
// ---------------------------------------------------------------------------
extern "C" void kernel_launch(void* const* d_in, const int* in_sizes, int n_in,
                              void* d_out, int out_size) {
    const int*   text = (const int*)d_in[0];
    const float* W    = (const float*)d_in[1];
    const float* bias = (const float*)d_in[2];
    float*       out  = (float*)d_out;

    bow_prep_kernel<<<TR_BLOCKS + B_SZ, 256>>>(W, text);
    bow_gather_kernel<<<B_SZ, 256>>>(bias, out);
}